// round 11
// baseline (speedup 1.0000x reference)
#include <cuda_runtime.h>
#include <math.h>

#define B_    64
#define T_    256
#define F_IN_ 2048
#define H_    1024
#define G3    3072
#define SPLITS 16
#define KS    (H_ / SPLITS)   // 64

#define NBLK   384            // 24 col-tiles x 16 k-splits, all co-resident
#define NTHR   128
#define SA_STRIDE 68          // 64 rows + pad (272B, 16B-aligned)
#define SB_STRIDE 132         // 128 cols + pad (528B, 16B-aligned)
#define SMEM_BYTES ((64 * SA_STRIDE + 64 * SB_STRIDE) * 4)   // 51200 B

typedef unsigned long long ull;

// ---------------- scratch (static device allocations; no cudaMalloc) ----------
__device__ float g_emb[B_ * T_ * H_];
__device__ float g_gx [B_ * T_ * G3];
__device__ float g_cp [SPLITS * B_ * G3];      // split-K partials
__device__ float g_h  [B_ * H_];               // hidden state
__device__ unsigned int g_bar_count;
__device__ volatile unsigned int g_bar_gen;

// ---------------- packed fp32x2 helpers ---------------------------------------
__device__ __forceinline__ ull splat2(float x) {
    ull r; unsigned int u = __float_as_uint(x);
    asm("mov.b64 %0, {%1, %1};" : "=l"(r) : "r"(u));
    return r;
}
__device__ __forceinline__ void ffma2(ull& d, ull a, ull b) {
    asm("fma.rn.f32x2 %0, %1, %2, %0;" : "+l"(d) : "l"(a), "l"(b));
}

__device__ __forceinline__ float fast_sigmoid(float x) {
    return 1.f / (1.f + __expf(-x));
}
__device__ __forceinline__ float fast_tanh(float x) {
    return 2.f / (1.f + __expf(-2.f * x)) - 1.f;
}

// ---------------- big SGEMM (double-buffered, f32x2): C = A @ B^T + bias ------
// BM=BN=128, BK=16, 8x8 micro (as 8 rows x 4 col-pairs), 256 threads.
__global__ __launch_bounds__(256) void sgemm_nt_bias(
    const float* __restrict__ A, const float* __restrict__ Bm,
    const float* __restrict__ bias, float* __restrict__ C,
    int M, int N, int K)
{
    __shared__ float As[2][16][128 + 4];
    __shared__ float Bs[2][16][128 + 4];
    const int tid = threadIdx.x;
    const int bm = blockIdx.y * 128;
    const int bn = blockIdx.x * 128;
    const int tx = tid & 15;
    const int ty = tid >> 4;

    const int lr0 = tid >> 2;
    const int lc0 = (tid & 3) << 2;
    const int lr1 = (tid + 256) >> 2;
    const int lc1 = ((tid + 256) & 3) << 2;

    ull accp[8][4];
#pragma unroll
    for (int i = 0; i < 8; i++)
#pragma unroll
        for (int j = 0; j < 4; j++) accp[i][j] = 0ull;

    {
        float4 va0 = *reinterpret_cast<const float4*>(&A[(size_t)(bm + lr0) * K + lc0]);
        float4 va1 = *reinterpret_cast<const float4*>(&A[(size_t)(bm + lr1) * K + lc1]);
        float4 vb0 = *reinterpret_cast<const float4*>(&Bm[(size_t)(bn + lr0) * K + lc0]);
        float4 vb1 = *reinterpret_cast<const float4*>(&Bm[(size_t)(bn + lr1) * K + lc1]);
        As[0][lc0 + 0][lr0] = va0.x; As[0][lc0 + 1][lr0] = va0.y; As[0][lc0 + 2][lr0] = va0.z; As[0][lc0 + 3][lr0] = va0.w;
        As[0][lc1 + 0][lr1] = va1.x; As[0][lc1 + 1][lr1] = va1.y; As[0][lc1 + 2][lr1] = va1.z; As[0][lc1 + 3][lr1] = va1.w;
        Bs[0][lc0 + 0][lr0] = vb0.x; Bs[0][lc0 + 1][lr0] = vb0.y; Bs[0][lc0 + 2][lr0] = vb0.z; Bs[0][lc0 + 3][lr0] = vb0.w;
        Bs[0][lc1 + 0][lr1] = vb1.x; Bs[0][lc1 + 1][lr1] = vb1.y; Bs[0][lc1 + 2][lr1] = vb1.z; Bs[0][lc1 + 3][lr1] = vb1.w;
    }
    __syncthreads();

    const int nch = K >> 4;
    for (int ch = 0; ch < nch; ch++) {
        const int cur = ch & 1, nxt = cur ^ 1;
        float4 pa0, pa1, pb0, pb1;
        const bool more = (ch + 1 < nch);
        if (more) {
            const int k0 = (ch + 1) << 4;
            pa0 = *reinterpret_cast<const float4*>(&A[(size_t)(bm + lr0) * K + k0 + lc0]);
            pa1 = *reinterpret_cast<const float4*>(&A[(size_t)(bm + lr1) * K + k0 + lc1]);
            pb0 = *reinterpret_cast<const float4*>(&Bm[(size_t)(bn + lr0) * K + k0 + lc0]);
            pb1 = *reinterpret_cast<const float4*>(&Bm[(size_t)(bn + lr1) * K + k0 + lc1]);
        }
#pragma unroll
        for (int k = 0; k < 16; k++) {
            float ar[8];
            *reinterpret_cast<float4*>(ar)     = *reinterpret_cast<const float4*>(&As[cur][k][ty * 8]);
            *reinterpret_cast<float4*>(ar + 4) = *reinterpret_cast<const float4*>(&As[cur][k][ty * 8 + 4]);
            ulonglong2 b01 = *reinterpret_cast<const ulonglong2*>(&Bs[cur][k][tx * 8]);
            ulonglong2 b23 = *reinterpret_cast<const ulonglong2*>(&Bs[cur][k][tx * 8 + 4]);
#pragma unroll
            for (int i = 0; i < 8; i++) {
                const ull a2 = splat2(ar[i]);
                ffma2(accp[i][0], a2, b01.x);
                ffma2(accp[i][1], a2, b01.y);
                ffma2(accp[i][2], a2, b23.x);
                ffma2(accp[i][3], a2, b23.y);
            }
        }
        if (more) {
            As[nxt][lc0 + 0][lr0] = pa0.x; As[nxt][lc0 + 1][lr0] = pa0.y; As[nxt][lc0 + 2][lr0] = pa0.z; As[nxt][lc0 + 3][lr0] = pa0.w;
            As[nxt][lc1 + 0][lr1] = pa1.x; As[nxt][lc1 + 1][lr1] = pa1.y; As[nxt][lc1 + 2][lr1] = pa1.z; As[nxt][lc1 + 3][lr1] = pa1.w;
            Bs[nxt][lc0 + 0][lr0] = pb0.x; Bs[nxt][lc0 + 1][lr0] = pb0.y; Bs[nxt][lc0 + 2][lr0] = pb0.z; Bs[nxt][lc0 + 3][lr0] = pb0.w;
            Bs[nxt][lc1 + 0][lr1] = pb1.x; Bs[nxt][lc1 + 1][lr1] = pb1.y; Bs[nxt][lc1 + 2][lr1] = pb1.z; Bs[nxt][lc1 + 3][lr1] = pb1.w;
        }
        __syncthreads();
    }

    const int row0 = bm + ty * 8;
    const int col0 = bn + tx * 8;
    float bb[8];
#pragma unroll
    for (int j = 0; j < 8; j++) bb[j] = bias[col0 + j];
#pragma unroll
    for (int i = 0; i < 8; i++) {
        float2 p0 = *reinterpret_cast<float2*>(&accp[i][0]);
        float2 p1 = *reinterpret_cast<float2*>(&accp[i][1]);
        float2 p2 = *reinterpret_cast<float2*>(&accp[i][2]);
        float2 p3 = *reinterpret_cast<float2*>(&accp[i][3]);
        float4 v0, v1;
        v0.x = p0.x + bb[0]; v0.y = p0.y + bb[1];
        v0.z = p1.x + bb[2]; v0.w = p1.y + bb[3];
        v1.x = p2.x + bb[4]; v1.y = p2.y + bb[5];
        v1.z = p3.x + bb[6]; v1.w = p3.y + bb[7];
        *reinterpret_cast<float4*>(&C[(size_t)(row0 + i) * N + col0])     = v0;
        *reinterpret_cast<float4*>(&C[(size_t)(row0 + i) * N + col0 + 4]) = v1;
    }
}

// ---------------- grid-wide barrier (nanosleep backoff) -----------------------
__device__ __forceinline__ void grid_barrier()
{
    __syncthreads();
    if (threadIdx.x == 0) {
        __threadfence();
        unsigned int gen = g_bar_gen;
        unsigned int t = atomicAdd(&g_bar_count, 1u);
        if (t == NBLK - 1) {
            g_bar_count = 0;
            __threadfence();
            g_bar_gen = gen + 1;
        } else {
            while (g_bar_gen == gen) { __nanosleep(64); }
        }
        __threadfence();
    }
    __syncthreads();
}

// ---------------- persistent GRU scan: SMEM-resident w_hh + f32x2 -------------
__global__ void __launch_bounds__(NTHR, 3) gru_scan_persistent(
    const float* __restrict__ gx, const float* __restrict__ Whh,
    const float* __restrict__ b_hh, const int* __restrict__ lens,
    float* __restrict__ out)
{
    extern __shared__ float smem[];
    float* sA = smem;                    // [64][SA_STRIDE]  h slice (k-major)
    float* sB = smem + 64 * SA_STRIDE;   // [64][SB_STRIDE]  w_hh slab (k-major)

    const int bid = blockIdx.x;
    const int tid = threadIdx.x;
    const int gtid = bid * NTHR + tid;
    const int tx = tid & 15;
    const int ty = tid >> 4;
    const int bn = (bid % 24) * 128;
    const int kbase = (bid / 24) * KS;
    const int sp = bid / 24;

    // ---- load w_hh slab into smem ONCE: sB[k][col] = Whh[bn+col][kbase+k] ----
    for (int i = tid; i < 128 * 16; i += NTHR) {
        const int col = i >> 4;
        const int k4  = (i & 15) << 2;
        const float4 w = __ldcg(reinterpret_cast<const float4*>(
            &Whh[(size_t)(bn + col) * H_ + kbase + k4]));
        sB[(k4 + 0) * SB_STRIDE + col] = w.x;
        sB[(k4 + 1) * SB_STRIDE + col] = w.y;
        sB[(k4 + 2) * SB_STRIDE + col] = w.z;
        sB[(k4 + 3) * SB_STRIDE + col] = w.w;
    }

    // ---- h0 = 0 ----
    for (int i = gtid; i < B_ * H_; i += NBLK * NTHR) g_h[i] = 0.f;
    grid_barrier();

    float* Cp = g_cp + (size_t)sp * (B_ * G3);

    for (int t = 0; t < T_; t++) {
        // ======== phase A: stage h slice, GEMM tile (f32x2) ========
        for (int i = tid; i < 64 * 16; i += NTHR) {
            const int r  = i >> 4;
            const int k4 = (i & 15) << 2;
            const float4 a = __ldcg(reinterpret_cast<const float4*>(
                &g_h[r * H_ + kbase + k4]));
            sA[(k4 + 0) * SA_STRIDE + r] = a.x;
            sA[(k4 + 1) * SA_STRIDE + r] = a.y;
            sA[(k4 + 2) * SA_STRIDE + r] = a.z;
            sA[(k4 + 3) * SA_STRIDE + r] = a.w;
        }
        __syncthreads();

        ull accp[8][4];
#pragma unroll
        for (int i = 0; i < 8; i++)
#pragma unroll
            for (int j = 0; j < 4; j++) accp[i][j] = 0ull;

#pragma unroll 4
        for (int k = 0; k < KS; k++) {
            float ar[8];
            *reinterpret_cast<float4*>(ar)     = *reinterpret_cast<const float4*>(&sA[k * SA_STRIDE + ty * 8]);
            *reinterpret_cast<float4*>(ar + 4) = *reinterpret_cast<const float4*>(&sA[k * SA_STRIDE + ty * 8 + 4]);
            ulonglong2 b01 = *reinterpret_cast<const ulonglong2*>(&sB[k * SB_STRIDE + tx * 8]);
            ulonglong2 b23 = *reinterpret_cast<const ulonglong2*>(&sB[k * SB_STRIDE + tx * 8 + 4]);
#pragma unroll
            for (int i = 0; i < 8; i++) {
                const ull a2 = splat2(ar[i]);
                ffma2(accp[i][0], a2, b01.x);
                ffma2(accp[i][1], a2, b01.y);
                ffma2(accp[i][2], a2, b23.x);
                ffma2(accp[i][3], a2, b23.y);
            }
        }

        const int row0 = ty * 8;
        const int col0 = bn + tx * 8;
#pragma unroll
        for (int i = 0; i < 8; i++) {
            float2 p0 = *reinterpret_cast<float2*>(&accp[i][0]);
            float2 p1 = *reinterpret_cast<float2*>(&accp[i][1]);
            float2 p2 = *reinterpret_cast<float2*>(&accp[i][2]);
            float2 p3 = *reinterpret_cast<float2*>(&accp[i][3]);
            float4 v0, v1;
            v0.x = p0.x; v0.y = p0.y; v0.z = p1.x; v0.w = p1.y;
            v1.x = p2.x; v1.y = p2.y; v1.z = p3.x; v1.w = p3.y;
            __stcg(reinterpret_cast<float4*>(&Cp[(size_t)(row0 + i) * G3 + col0]), v0);
            __stcg(reinterpret_cast<float4*>(&Cp[(size_t)(row0 + i) * G3 + col0 + 4]), v1);
        }
        grid_barrier();

        // ======== phase B: reduce + gates + update (first 16384 threads) ======
        if (gtid < 16384) {
            const int v = gtid;
            const int b = v >> 8;
            const int j4 = (v & 255) << 2;

            float4 ghr = make_float4(0.f, 0.f, 0.f, 0.f);
            float4 ghz = ghr, ghn = ghr;
#pragma unroll
            for (int s = 0; s < SPLITS; s++) {
                const float* base = g_cp + (size_t)s * (B_ * G3) + (size_t)b * G3 + j4;
                const float4 a = __ldcg(reinterpret_cast<const float4*>(base));
                const float4 c = __ldcg(reinterpret_cast<const float4*>(base + H_));
                const float4 d = __ldcg(reinterpret_cast<const float4*>(base + 2 * H_));
                ghr.x += a.x; ghr.y += a.y; ghr.z += a.z; ghr.w += a.w;
                ghz.x += c.x; ghz.y += c.y; ghz.z += c.z; ghz.w += c.w;
                ghn.x += d.x; ghn.y += d.y; ghn.z += d.z; ghn.w += d.w;
            }
            const float4 br = *reinterpret_cast<const float4*>(&b_hh[j4]);
            const float4 bz = *reinterpret_cast<const float4*>(&b_hh[H_ + j4]);
            const float4 bn2 = *reinterpret_cast<const float4*>(&b_hh[2 * H_ + j4]);

            const float* gxb = gx + ((size_t)b * T_ + t) * G3 + j4;
            const float4 xr = __ldcg(reinterpret_cast<const float4*>(gxb));
            const float4 xz = __ldcg(reinterpret_cast<const float4*>(gxb + H_));
            const float4 xn = __ldcg(reinterpret_cast<const float4*>(gxb + 2 * H_));

            const float4 hp = __ldcg(reinterpret_cast<const float4*>(&g_h[b * H_ + j4]));
            const bool m = t < lens[b];

            float4 hn;
            {
                float r = fast_sigmoid(xr.x + ghr.x + br.x);
                float z = fast_sigmoid(xz.x + ghz.x + bz.x);
                float n = fast_tanh(xn.x + r * (ghn.x + bn2.x));
                hn.x = (1.f - z) * n + z * hp.x;
            }
            {
                float r = fast_sigmoid(xr.y + ghr.y + br.y);
                float z = fast_sigmoid(xz.y + ghz.y + bz.y);
                float n = fast_tanh(xn.y + r * (ghn.y + bn2.y));
                hn.y = (1.f - z) * n + z * hp.y;
            }
            {
                float r = fast_sigmoid(xr.z + ghr.z + br.z);
                float z = fast_sigmoid(xz.z + ghz.z + bz.z);
                float n = fast_tanh(xn.z + r * (ghn.z + bn2.z));
                hn.z = (1.f - z) * n + z * hp.z;
            }
            {
                float r = fast_sigmoid(xr.w + ghr.w + br.w);
                float z = fast_sigmoid(xz.w + ghz.w + bz.w);
                float n = fast_tanh(xn.w + r * (ghn.w + bn2.w));
                hn.w = (1.f - z) * n + z * hp.w;
            }

            const float4 hout = m ? hn : hp;
            const float4 yout = m ? hn : make_float4(0.f, 0.f, 0.f, 0.f);
            __stcg(reinterpret_cast<float4*>(&g_h[b * H_ + j4]), hout);
            __stcg(reinterpret_cast<float4*>(&out[((size_t)b * T_ + t) * H_ + j4]), yout);
        }
        grid_barrier();
    }

    // hidden = output[:, T-1, :]
    for (int idx = gtid; idx < B_ * H_; idx += NBLK * NTHR) {
        const int b = idx >> 10;
        const int j = idx & 1023;
        out[(size_t)B_ * T_ * H_ + idx] =
            __ldcg(&out[((size_t)b * T_ + (T_ - 1)) * H_ + j]);
    }
}

// ---------------- launch ------------------------------------------------------
extern "C" void kernel_launch(void* const* d_in, const int* in_sizes, int n_in,
                              void* d_out, int out_size)
{
    const float* input = (const float*)d_in[0];
    const int*   lens  = (const int*)  d_in[1];
    const float* W_p   = (const float*)d_in[2];
    const float* b_p   = (const float*)d_in[3];
    const float* w_ih  = (const float*)d_in[4];
    const float* w_hh  = (const float*)d_in[5];
    const float* b_ih  = (const float*)d_in[6];
    const float* b_hh  = (const float*)d_in[7];
    float* out = (float*)d_out;

    float *emb, *gx;
    cudaGetSymbolAddress((void**)&emb, g_emb);
    cudaGetSymbolAddress((void**)&gx,  g_gx);

    // emb = input @ W_p^T + b_p          [16384 x 1024], K=2048
    dim3 g1(H_ / 128, (B_ * T_) / 128);
    sgemm_nt_bias<<<g1, 256>>>(input, W_p, b_p, emb, B_ * T_, H_, F_IN_);

    // gx = emb @ w_ih^T + b_ih           [16384 x 3072], K=1024
    dim3 g2(G3 / 128, (B_ * T_) / 128);
    sgemm_nt_bias<<<g2, 256>>>(emb, w_ih, b_ih, gx, B_ * T_, G3, H_);

    // persistent fused scan (h0 init + 256 steps + hidden copy)
    static int smem_set = 0;
    if (!smem_set) {
        cudaFuncSetAttribute(gru_scan_persistent,
                             cudaFuncAttributeMaxDynamicSharedMemorySize, SMEM_BYTES);
        smem_set = 1;
    }
    gru_scan_persistent<<<NBLK, NTHR, SMEM_BYTES>>>(gx, w_hh, b_hh, lens, out);
}

// round 15
// speedup vs baseline: 1.2455x; 1.2455x over previous
#include <cuda_runtime.h>
#include <math.h>

#define B_    64
#define T_    256
#define F_IN_ 2048
#define H_    1024
#define G3    3072
#define SPLITS 16
#define KS    (H_ / SPLITS)   // 64

#define NBLK   384            // 24 col-tiles x 16 k-splits, all co-resident
#define NTHR   256
#define NGATE  64             // blocks that run phase B (64*256 = 16384 threads)
#define SA_STRIDE 68          // 64 rows + pad (272B, 16B-aligned)
#define SB_STRIDE 132         // 128 cols + pad (528B, 16B-aligned)
#define SMEM_BYTES ((64 * SA_STRIDE + 64 * SB_STRIDE) * 4)   // 51200 B

// ---------------- scratch (static device allocations; no cudaMalloc) ----------
__device__ float g_emb[B_ * T_ * H_];
__device__ float g_gx [B_ * T_ * G3];
__device__ float g_cp [SPLITS * B_ * G3];      // split-K partials
__device__ float g_h  [B_ * H_];               // hidden state
__device__ unsigned int g_cnt0, g_cnt1, g_cnt2;
__device__ volatile unsigned int g_gen0, g_gen1, g_gen2;

__device__ __forceinline__ float fast_sigmoid(float x) {
    return 1.f / (1.f + __expf(-x));
}
__device__ __forceinline__ float fast_tanh(float x) {
    return 2.f / (1.f + __expf(-2.f * x)) - 1.f;
}

// ---------------- big SGEMM (double-buffered): C = A @ B^T + bias -------------
__global__ __launch_bounds__(256) void sgemm_nt_bias(
    const float* __restrict__ A, const float* __restrict__ Bm,
    const float* __restrict__ bias, float* __restrict__ C,
    int M, int N, int K)
{
    __shared__ float As[2][16][128 + 4];
    __shared__ float Bs[2][16][128 + 4];
    const int tid = threadIdx.x;
    const int bm = blockIdx.y * 128;
    const int bn = blockIdx.x * 128;
    const int tx = tid & 15;
    const int ty = tid >> 4;

    const int lr0 = tid >> 2;
    const int lc0 = (tid & 3) << 2;
    const int lr1 = (tid + 256) >> 2;
    const int lc1 = ((tid + 256) & 3) << 2;

    float acc[8][8];
#pragma unroll
    for (int i = 0; i < 8; i++)
#pragma unroll
        for (int j = 0; j < 8; j++) acc[i][j] = 0.f;

    {
        float4 va0 = *reinterpret_cast<const float4*>(&A[(size_t)(bm + lr0) * K + lc0]);
        float4 va1 = *reinterpret_cast<const float4*>(&A[(size_t)(bm + lr1) * K + lc1]);
        float4 vb0 = *reinterpret_cast<const float4*>(&Bm[(size_t)(bn + lr0) * K + lc0]);
        float4 vb1 = *reinterpret_cast<const float4*>(&Bm[(size_t)(bn + lr1) * K + lc1]);
        As[0][lc0 + 0][lr0] = va0.x; As[0][lc0 + 1][lr0] = va0.y; As[0][lc0 + 2][lr0] = va0.z; As[0][lc0 + 3][lr0] = va0.w;
        As[0][lc1 + 0][lr1] = va1.x; As[0][lc1 + 1][lr1] = va1.y; As[0][lc1 + 2][lr1] = va1.z; As[0][lc1 + 3][lr1] = va1.w;
        Bs[0][lc0 + 0][lr0] = vb0.x; Bs[0][lc0 + 1][lr0] = vb0.y; Bs[0][lc0 + 2][lr0] = vb0.z; Bs[0][lc0 + 3][lr0] = vb0.w;
        Bs[0][lc1 + 0][lr1] = vb1.x; Bs[0][lc1 + 1][lr1] = vb1.y; Bs[0][lc1 + 2][lr1] = vb1.z; Bs[0][lc1 + 3][lr1] = vb1.w;
    }
    __syncthreads();

    const int nch = K >> 4;
    for (int ch = 0; ch < nch; ch++) {
        const int cur = ch & 1, nxt = cur ^ 1;
        float4 pa0, pa1, pb0, pb1;
        const bool more = (ch + 1 < nch);
        if (more) {
            const int k0 = (ch + 1) << 4;
            pa0 = *reinterpret_cast<const float4*>(&A[(size_t)(bm + lr0) * K + k0 + lc0]);
            pa1 = *reinterpret_cast<const float4*>(&A[(size_t)(bm + lr1) * K + k0 + lc1]);
            pb0 = *reinterpret_cast<const float4*>(&Bm[(size_t)(bn + lr0) * K + k0 + lc0]);
            pb1 = *reinterpret_cast<const float4*>(&Bm[(size_t)(bn + lr1) * K + k0 + lc1]);
        }
#pragma unroll
        for (int k = 0; k < 16; k++) {
            float ar[8], br[8];
            *reinterpret_cast<float4*>(ar)     = *reinterpret_cast<const float4*>(&As[cur][k][ty * 8]);
            *reinterpret_cast<float4*>(ar + 4) = *reinterpret_cast<const float4*>(&As[cur][k][ty * 8 + 4]);
            *reinterpret_cast<float4*>(br)     = *reinterpret_cast<const float4*>(&Bs[cur][k][tx * 8]);
            *reinterpret_cast<float4*>(br + 4) = *reinterpret_cast<const float4*>(&Bs[cur][k][tx * 8 + 4]);
#pragma unroll
            for (int i = 0; i < 8; i++)
#pragma unroll
                for (int j = 0; j < 8; j++)
                    acc[i][j] += ar[i] * br[j];
        }
        if (more) {
            As[nxt][lc0 + 0][lr0] = pa0.x; As[nxt][lc0 + 1][lr0] = pa0.y; As[nxt][lc0 + 2][lr0] = pa0.z; As[nxt][lc0 + 3][lr0] = pa0.w;
            As[nxt][lc1 + 0][lr1] = pa1.x; As[nxt][lc1 + 1][lr1] = pa1.y; As[nxt][lc1 + 2][lr1] = pa1.z; As[nxt][lc1 + 3][lr1] = pa1.w;
            Bs[nxt][lc0 + 0][lr0] = pb0.x; Bs[nxt][lc0 + 1][lr0] = pb0.y; Bs[nxt][lc0 + 2][lr0] = pb0.z; Bs[nxt][lc0 + 3][lr0] = pb0.w;
            Bs[nxt][lc1 + 0][lr1] = pb1.x; Bs[nxt][lc1 + 1][lr1] = pb1.y; Bs[nxt][lc1 + 2][lr1] = pb1.z; Bs[nxt][lc1 + 3][lr1] = pb1.w;
        }
        __syncthreads();
    }

    const int row0 = bm + ty * 8;
    const int col0 = bn + tx * 8;
    float bb[8];
#pragma unroll
    for (int j = 0; j < 8; j++) bb[j] = bias[col0 + j];
#pragma unroll
    for (int i = 0; i < 8; i++) {
        float4 v0, v1;
        v0.x = acc[i][0] + bb[0]; v0.y = acc[i][1] + bb[1];
        v0.z = acc[i][2] + bb[2]; v0.w = acc[i][3] + bb[3];
        v1.x = acc[i][4] + bb[4]; v1.y = acc[i][5] + bb[5];
        v1.z = acc[i][6] + bb[6]; v1.w = acc[i][7] + bb[7];
        *reinterpret_cast<float4*>(&C[(size_t)(row0 + i) * N + col0])     = v0;
        *reinterpret_cast<float4*>(&C[(size_t)(row0 + i) * N + col0 + 4]) = v1;
    }
}

// ---------------- barrier primitives ------------------------------------------
// full barrier (init/tail): all arrive, all wait
__device__ __forceinline__ void full_barrier()
{
    __syncthreads();
    if (threadIdx.x == 0) {
        __threadfence();
        unsigned int gen = g_gen0;
        unsigned int t = atomicAdd(&g_cnt0, 1u);
        if (t == NBLK - 1) {
            g_cnt0 = 0;
            __threadfence();
            g_gen0 = gen + 1;
        } else {
            while (g_gen0 == gen) { __nanosleep(64); }
        }
        __threadfence();
    }
    __syncthreads();
}

// ---------------- persistent GRU scan: SMEM-resident w_hh ---------------------
// Phase A: 384 tile-blocks (256 thr, 4x8 micro) -> partials.
// bar1: 384 arrive, 64 gate blocks wait.  Phase B (64 blocks): gate+h+y.
// bar2: 64 arrive, 384 wait.
__global__ void __launch_bounds__(NTHR, 3) gru_scan_persistent(
    const float* __restrict__ gx, const float* __restrict__ Whh,
    const float* __restrict__ b_hh, const int* __restrict__ lens,
    float* __restrict__ out)
{
    extern __shared__ float smem[];
    float* sA = smem;                    // [64][SA_STRIDE]  h slice (k-major)
    float* sB = smem + 64 * SA_STRIDE;   // [64][SB_STRIDE]  w_hh slab (k-major)

    const int bid = blockIdx.x;
    const int tid = threadIdx.x;
    const int gtid = bid * NTHR + tid;
    const int tx = tid & 15;             // col micro (8 cols)
    const int ty = tid >> 4;             // row micro (4 rows)
    const int bn = (bid % 24) * 128;
    const int kbase = (bid / 24) * KS;
    const int sp = bid / 24;
    const bool is_gate = (bid < NGATE);

    // ---- load w_hh slab into smem ONCE: sB[k][col] = Whh[bn+col][kbase+k] ----
    for (int i = tid; i < 128 * 16; i += NTHR) {
        const int col = i >> 4;
        const int k4  = (i & 15) << 2;
        const float4 w = __ldcg(reinterpret_cast<const float4*>(
            &Whh[(size_t)(bn + col) * H_ + kbase + k4]));
        sB[(k4 + 0) * SB_STRIDE + col] = w.x;
        sB[(k4 + 1) * SB_STRIDE + col] = w.y;
        sB[(k4 + 2) * SB_STRIDE + col] = w.z;
        sB[(k4 + 3) * SB_STRIDE + col] = w.w;
    }

    // ---- h0 = 0 ----
    for (int i = gtid; i < B_ * H_; i += NBLK * NTHR) g_h[i] = 0.f;
    full_barrier();

    float* Cp = g_cp + (size_t)sp * (B_ * G3);

    for (int t = 0; t < T_; t++) {
        // read both generations BEFORE any arrival this step (deadlock-safe)
        unsigned int gen1, gen2;
        if (tid == 0) { gen1 = g_gen1; gen2 = g_gen2; }

        // ======== phase A: stage h slice, GEMM tile ========
        for (int i = tid; i < 64 * 16; i += NTHR) {
            const int r  = i >> 4;
            const int k4 = (i & 15) << 2;
            const float4 a = __ldcg(reinterpret_cast<const float4*>(
                &g_h[r * H_ + kbase + k4]));
            sA[(k4 + 0) * SA_STRIDE + r] = a.x;
            sA[(k4 + 1) * SA_STRIDE + r] = a.y;
            sA[(k4 + 2) * SA_STRIDE + r] = a.z;
            sA[(k4 + 3) * SA_STRIDE + r] = a.w;
        }
        __syncthreads();

        float acc[4][8];
#pragma unroll
        for (int i = 0; i < 4; i++)
#pragma unroll
            for (int j = 0; j < 8; j++) acc[i][j] = 0.f;

#pragma unroll 8
        for (int k = 0; k < KS; k++) {
            float ar[4], br[8];
            *reinterpret_cast<float4*>(ar)     = *reinterpret_cast<const float4*>(&sA[k * SA_STRIDE + ty * 4]);
            *reinterpret_cast<float4*>(br)     = *reinterpret_cast<const float4*>(&sB[k * SB_STRIDE + tx * 8]);
            *reinterpret_cast<float4*>(br + 4) = *reinterpret_cast<const float4*>(&sB[k * SB_STRIDE + tx * 8 + 4]);
#pragma unroll
            for (int i = 0; i < 4; i++)
#pragma unroll
                for (int j = 0; j < 8; j++)
                    acc[i][j] += ar[i] * br[j];
        }

        const int row0 = ty * 4;
        const int col0 = bn + tx * 8;
#pragma unroll
        for (int i = 0; i < 4; i++) {
            float4 v0, v1;
            v0.x = acc[i][0]; v0.y = acc[i][1]; v0.z = acc[i][2]; v0.w = acc[i][3];
            v1.x = acc[i][4]; v1.y = acc[i][5]; v1.z = acc[i][6]; v1.w = acc[i][7];
            __stcg(reinterpret_cast<float4*>(&Cp[(size_t)(row0 + i) * G3 + col0]), v0);
            __stcg(reinterpret_cast<float4*>(&Cp[(size_t)(row0 + i) * G3 + col0 + 4]), v1);
        }

        // ---- bar1: all 384 arrive; only gate blocks wait ----
        __syncthreads();
        if (tid == 0) {
            __threadfence();
            unsigned int a1 = atomicAdd(&g_cnt1, 1u);
            if (a1 == NBLK - 1) {
                g_cnt1 = 0;
                __threadfence();
                g_gen1 = gen1 + 1;
            } else if (is_gate) {
                while (g_gen1 == gen1) { __nanosleep(32); }
            }
            __threadfence();
        }
        __syncthreads();

        // ======== phase B: gate blocks only ========
        if (is_gate) {
            const int v = gtid;                  // 0..16383
            const int b = v >> 8;
            const int j4 = (v & 255) << 2;

            float4 ghr = make_float4(0.f, 0.f, 0.f, 0.f);
            float4 ghz = ghr, ghn = ghr;
#pragma unroll
            for (int s = 0; s < SPLITS; s++) {
                const float* base = g_cp + (size_t)s * (B_ * G3) + (size_t)b * G3 + j4;
                const float4 a = __ldcg(reinterpret_cast<const float4*>(base));
                const float4 c = __ldcg(reinterpret_cast<const float4*>(base + H_));
                const float4 d = __ldcg(reinterpret_cast<const float4*>(base + 2 * H_));
                ghr.x += a.x; ghr.y += a.y; ghr.z += a.z; ghr.w += a.w;
                ghz.x += c.x; ghz.y += c.y; ghz.z += c.z; ghz.w += c.w;
                ghn.x += d.x; ghn.y += d.y; ghn.z += d.z; ghn.w += d.w;
            }
            const float4 br = *reinterpret_cast<const float4*>(&b_hh[j4]);
            const float4 bz = *reinterpret_cast<const float4*>(&b_hh[H_ + j4]);
            const float4 bn2 = *reinterpret_cast<const float4*>(&b_hh[2 * H_ + j4]);

            const float* gxb = gx + ((size_t)b * T_ + t) * G3 + j4;
            const float4 xr = __ldcg(reinterpret_cast<const float4*>(gxb));
            const float4 xz = __ldcg(reinterpret_cast<const float4*>(gxb + H_));
            const float4 xn = __ldcg(reinterpret_cast<const float4*>(gxb + 2 * H_));

            const float4 hp = __ldcg(reinterpret_cast<const float4*>(&g_h[b * H_ + j4]));
            const bool m = t < lens[b];

            float4 hn;
            {
                float r = fast_sigmoid(xr.x + ghr.x + br.x);
                float z = fast_sigmoid(xz.x + ghz.x + bz.x);
                float n = fast_tanh(xn.x + r * (ghn.x + bn2.x));
                hn.x = (1.f - z) * n + z * hp.x;
            }
            {
                float r = fast_sigmoid(xr.y + ghr.y + br.y);
                float z = fast_sigmoid(xz.y + ghz.y + bz.y);
                float n = fast_tanh(xn.y + r * (ghn.y + bn2.y));
                hn.y = (1.f - z) * n + z * hp.y;
            }
            {
                float r = fast_sigmoid(xr.z + ghr.z + br.z);
                float z = fast_sigmoid(xz.z + ghz.z + bz.z);
                float n = fast_tanh(xn.z + r * (ghn.z + bn2.z));
                hn.z = (1.f - z) * n + z * hp.z;
            }
            {
                float r = fast_sigmoid(xr.w + ghr.w + br.w);
                float z = fast_sigmoid(xz.w + ghz.w + bz.w);
                float n = fast_tanh(xn.w + r * (ghn.w + bn2.w));
                hn.w = (1.f - z) * n + z * hp.w;
            }

            const float4 hout = m ? hn : hp;
            const float4 yout = m ? hn : make_float4(0.f, 0.f, 0.f, 0.f);
            __stcg(reinterpret_cast<float4*>(&g_h[b * H_ + j4]), hout);
            __stcg(reinterpret_cast<float4*>(&out[((size_t)b * T_ + t) * H_ + j4]), yout);
        }

        // ---- bar2: gate blocks arrive; everyone waits ----
        __syncthreads();
        if (tid == 0) {
            __threadfence();
            if (is_gate) {
                unsigned int a2 = atomicAdd(&g_cnt2, 1u);
                if (a2 == NGATE - 1) {
                    g_cnt2 = 0;
                    __threadfence();
                    g_gen2 = gen2 + 1;
                } else {
                    while (g_gen2 == gen2) { __nanosleep(32); }
                }
            } else {
                while (g_gen2 == gen2) { __nanosleep(64); }
            }
            __threadfence();
        }
        __syncthreads();
    }

    // hidden = output[:, T-1, :]
    for (int idx = gtid; idx < B_ * H_; idx += NBLK * NTHR) {
        const int b = idx >> 10;
        const int j = idx & 1023;
        out[(size_t)B_ * T_ * H_ + idx] =
            __ldcg(&out[((size_t)b * T_ + (T_ - 1)) * H_ + j]);
    }
}

// ---------------- launch ------------------------------------------------------
extern "C" void kernel_launch(void* const* d_in, const int* in_sizes, int n_in,
                              void* d_out, int out_size)
{
    const float* input = (const float*)d_in[0];
    const int*   lens  = (const int*)  d_in[1];
    const float* W_p   = (const float*)d_in[2];
    const float* b_p   = (const float*)d_in[3];
    const float* w_ih  = (const float*)d_in[4];
    const float* w_hh  = (const float*)d_in[5];
    const float* b_ih  = (const float*)d_in[6];
    const float* b_hh  = (const float*)d_in[7];
    float* out = (float*)d_out;

    float *emb, *gx;
    cudaGetSymbolAddress((void**)&emb, g_emb);
    cudaGetSymbolAddress((void**)&gx,  g_gx);

    // emb = input @ W_p^T + b_p          [16384 x 1024], K=2048
    dim3 g1(H_ / 128, (B_ * T_) / 128);
    sgemm_nt_bias<<<g1, 256>>>(input, W_p, b_p, emb, B_ * T_, H_, F_IN_);

    // gx = emb @ w_ih^T + b_ih           [16384 x 3072], K=1024
    dim3 g2(G3 / 128, (B_ * T_) / 128);
    sgemm_nt_bias<<<g2, 256>>>(emb, w_ih, b_ih, gx, B_ * T_, G3, H_);

    // persistent fused scan (h0 init + 256 steps + hidden copy)
    static int smem_set = 0;
    if (!smem_set) {
        cudaFuncSetAttribute(gru_scan_persistent,
                             cudaFuncAttributeMaxDynamicSharedMemorySize, SMEM_BYTES);
        smem_set = 1;
    }
    gru_scan_persistent<<<NBLK, NTHR, SMEM_BYTES>>>(gx, w_hh, b_hh, lens, out);
}

// round 16
// speedup vs baseline: 1.4248x; 1.1439x over previous
#include <cuda_runtime.h>
#include <math.h>

#define B_    64
#define T_    256
#define F_IN_ 2048
#define H_    1024
#define G3    3072
#define SPLITS 16
#define KS    (H_ / SPLITS)   // 64

#define NBLK   384            // 24 col-tiles x 16 k-splits, all co-resident
#define NTHR   128
#define SA_STRIDE 68          // 64 rows + pad (272B, 16B-aligned)
#define SB_STRIDE 132         // 128 cols + pad (528B, 16B-aligned)
#define SMEM_BYTES ((64 * SA_STRIDE + 64 * SB_STRIDE) * 4)   // 51200 B

// ---------------- scratch (static device allocations; no cudaMalloc) ----------
__device__ float g_emb[B_ * T_ * H_];
__device__ float g_gx [B_ * T_ * G3];
__device__ float g_cp [SPLITS * B_ * G3];      // split-K partials
__device__ float g_h  [B_ * H_];               // hidden state
// barrier words on SEPARATE 128B L2 lines: atomics on count must not collide
// with the generation line that 384 blocks poll.
__device__ unsigned int g_bar_count_pad[64];            // [0] used
__device__ volatile unsigned int g_bar_gen_pad[64];     // [0] used, different line

__device__ __forceinline__ float fast_sigmoid(float x) {
    return 1.f / (1.f + __expf(-x));
}
__device__ __forceinline__ float fast_tanh(float x) {
    return 2.f / (1.f + __expf(-2.f * x)) - 1.f;
}

// ---------------- big SGEMM (double-buffered): C = A @ B^T + bias -------------
__global__ __launch_bounds__(256) void sgemm_nt_bias(
    const float* __restrict__ A, const float* __restrict__ Bm,
    const float* __restrict__ bias, float* __restrict__ C,
    int M, int N, int K)
{
    __shared__ float As[2][16][128 + 4];
    __shared__ float Bs[2][16][128 + 4];
    const int tid = threadIdx.x;
    const int bm = blockIdx.y * 128;
    const int bn = blockIdx.x * 128;
    const int tx = tid & 15;
    const int ty = tid >> 4;

    const int lr0 = tid >> 2;
    const int lc0 = (tid & 3) << 2;
    const int lr1 = (tid + 256) >> 2;
    const int lc1 = ((tid + 256) & 3) << 2;

    float acc[8][8];
#pragma unroll
    for (int i = 0; i < 8; i++)
#pragma unroll
        for (int j = 0; j < 8; j++) acc[i][j] = 0.f;

    {
        float4 va0 = *reinterpret_cast<const float4*>(&A[(size_t)(bm + lr0) * K + lc0]);
        float4 va1 = *reinterpret_cast<const float4*>(&A[(size_t)(bm + lr1) * K + lc1]);
        float4 vb0 = *reinterpret_cast<const float4*>(&Bm[(size_t)(bn + lr0) * K + lc0]);
        float4 vb1 = *reinterpret_cast<const float4*>(&Bm[(size_t)(bn + lr1) * K + lc1]);
        As[0][lc0 + 0][lr0] = va0.x; As[0][lc0 + 1][lr0] = va0.y; As[0][lc0 + 2][lr0] = va0.z; As[0][lc0 + 3][lr0] = va0.w;
        As[0][lc1 + 0][lr1] = va1.x; As[0][lc1 + 1][lr1] = va1.y; As[0][lc1 + 2][lr1] = va1.z; As[0][lc1 + 3][lr1] = va1.w;
        Bs[0][lc0 + 0][lr0] = vb0.x; Bs[0][lc0 + 1][lr0] = vb0.y; Bs[0][lc0 + 2][lr0] = vb0.z; Bs[0][lc0 + 3][lr0] = vb0.w;
        Bs[0][lc1 + 0][lr1] = vb1.x; Bs[0][lc1 + 1][lr1] = vb1.y; Bs[0][lc1 + 2][lr1] = vb1.z; Bs[0][lc1 + 3][lr1] = vb1.w;
    }
    __syncthreads();

    const int nch = K >> 4;
    for (int ch = 0; ch < nch; ch++) {
        const int cur = ch & 1, nxt = cur ^ 1;
        float4 pa0, pa1, pb0, pb1;
        const bool more = (ch + 1 < nch);
        if (more) {
            const int k0 = (ch + 1) << 4;
            pa0 = *reinterpret_cast<const float4*>(&A[(size_t)(bm + lr0) * K + k0 + lc0]);
            pa1 = *reinterpret_cast<const float4*>(&A[(size_t)(bm + lr1) * K + k0 + lc1]);
            pb0 = *reinterpret_cast<const float4*>(&Bm[(size_t)(bn + lr0) * K + k0 + lc0]);
            pb1 = *reinterpret_cast<const float4*>(&Bm[(size_t)(bn + lr1) * K + k0 + lc1]);
        }
#pragma unroll
        for (int k = 0; k < 16; k++) {
            float ar[8], br[8];
            *reinterpret_cast<float4*>(ar)     = *reinterpret_cast<const float4*>(&As[cur][k][ty * 8]);
            *reinterpret_cast<float4*>(ar + 4) = *reinterpret_cast<const float4*>(&As[cur][k][ty * 8 + 4]);
            *reinterpret_cast<float4*>(br)     = *reinterpret_cast<const float4*>(&Bs[cur][k][tx * 8]);
            *reinterpret_cast<float4*>(br + 4) = *reinterpret_cast<const float4*>(&Bs[cur][k][tx * 8 + 4]);
#pragma unroll
            for (int i = 0; i < 8; i++)
#pragma unroll
                for (int j = 0; j < 8; j++)
                    acc[i][j] += ar[i] * br[j];
        }
        if (more) {
            As[nxt][lc0 + 0][lr0] = pa0.x; As[nxt][lc0 + 1][lr0] = pa0.y; As[nxt][lc0 + 2][lr0] = pa0.z; As[nxt][lc0 + 3][lr0] = pa0.w;
            As[nxt][lc1 + 0][lr1] = pa1.x; As[nxt][lc1 + 1][lr1] = pa1.y; As[nxt][lc1 + 2][lr1] = pa1.z; As[nxt][lc1 + 3][lr1] = pa1.w;
            Bs[nxt][lc0 + 0][lr0] = pb0.x; Bs[nxt][lc0 + 1][lr0] = pb0.y; Bs[nxt][lc0 + 2][lr0] = pb0.z; Bs[nxt][lc0 + 3][lr0] = pb0.w;
            Bs[nxt][lc1 + 0][lr1] = pb1.x; Bs[nxt][lc1 + 1][lr1] = pb1.y; Bs[nxt][lc1 + 2][lr1] = pb1.z; Bs[nxt][lc1 + 3][lr1] = pb1.w;
        }
        __syncthreads();
    }

    const int row0 = bm + ty * 8;
    const int col0 = bn + tx * 8;
    float bb[8];
#pragma unroll
    for (int j = 0; j < 8; j++) bb[j] = bias[col0 + j];
#pragma unroll
    for (int i = 0; i < 8; i++) {
        float4 v0, v1;
        v0.x = acc[i][0] + bb[0]; v0.y = acc[i][1] + bb[1];
        v0.z = acc[i][2] + bb[2]; v0.w = acc[i][3] + bb[3];
        v1.x = acc[i][4] + bb[4]; v1.y = acc[i][5] + bb[5];
        v1.z = acc[i][6] + bb[6]; v1.w = acc[i][7] + bb[7];
        *reinterpret_cast<float4*>(&C[(size_t)(row0 + i) * N + col0])     = v0;
        *reinterpret_cast<float4*>(&C[(size_t)(row0 + i) * N + col0 + 4]) = v1;
    }
}

// ---------------- grid-wide barrier (padded lines, empty spin) ----------------
__device__ __forceinline__ void grid_barrier()
{
    __syncthreads();
    if (threadIdx.x == 0) {
        __threadfence();
        unsigned int gen = g_bar_gen_pad[0];
        unsigned int t = atomicAdd(&g_bar_count_pad[0], 1u);
        if (t == NBLK - 1) {
            g_bar_count_pad[0] = 0;
            __threadfence();
            g_bar_gen_pad[0] = gen + 1;
        } else {
            while (g_bar_gen_pad[0] == gen) { }
        }
        __threadfence();
    }
    __syncthreads();
}

// ---------------- persistent GRU scan: SMEM-resident w_hh ---------------------
// Block bid owns w_hh cols [bn, bn+128) x k [kbase, kbase+64) in smem forever.
// Per step: phase A GEMM tile -> partials; barrier; phase B gate spread over
// ALL 384 blocks (block b handles tasks b + 384*i); barrier.
__global__ void __launch_bounds__(NTHR, 3) gru_scan_persistent(
    const float* __restrict__ gx, const float* __restrict__ Whh,
    const float* __restrict__ b_hh, const int* __restrict__ lens,
    float* __restrict__ out)
{
    extern __shared__ float smem[];
    float* sA = smem;                    // [64][SA_STRIDE]  h slice (k-major)
    float* sB = smem + 64 * SA_STRIDE;   // [64][SB_STRIDE]  w_hh slab (k-major)

    const int bid = blockIdx.x;
    const int tid = threadIdx.x;
    const int gtid = bid * NTHR + tid;
    const int tx = tid & 15;
    const int ty = tid >> 4;
    const int bn = (bid % 24) * 128;
    const int kbase = (bid / 24) * KS;
    const int sp = bid / 24;

    // gate task for this thread: task = bid + 384*tid, valid while < 16384
    const int gtask = bid + NBLK * tid;
    const bool has_gate = (gtask < 16384);
    const int gb = gtask >> 8;                 // batch row
    const int gj4 = (gtask & 255) << 2;        // j offset (float4)

    // ---- load w_hh slab into smem ONCE: sB[k][col] = Whh[bn+col][kbase+k] ----
    for (int i = tid; i < 128 * 16; i += NTHR) {
        const int col = i >> 4;
        const int k4  = (i & 15) << 2;
        const float4 w = __ldcg(reinterpret_cast<const float4*>(
            &Whh[(size_t)(bn + col) * H_ + kbase + k4]));
        sB[(k4 + 0) * SB_STRIDE + col] = w.x;
        sB[(k4 + 1) * SB_STRIDE + col] = w.y;
        sB[(k4 + 2) * SB_STRIDE + col] = w.z;
        sB[(k4 + 3) * SB_STRIDE + col] = w.w;
    }

    // ---- h0 = 0 ----
    for (int i = gtid; i < B_ * H_; i += NBLK * NTHR) g_h[i] = 0.f;
    grid_barrier();

    float* Cp = g_cp + (size_t)sp * (B_ * G3);

    for (int t = 0; t < T_; t++) {
        // ======== phase A: stage h slice, GEMM tile ========
        for (int i = tid; i < 64 * 16; i += NTHR) {
            const int r  = i >> 4;
            const int k4 = (i & 15) << 2;
            const float4 a = __ldcg(reinterpret_cast<const float4*>(
                &g_h[r * H_ + kbase + k4]));
            sA[(k4 + 0) * SA_STRIDE + r] = a.x;
            sA[(k4 + 1) * SA_STRIDE + r] = a.y;
            sA[(k4 + 2) * SA_STRIDE + r] = a.z;
            sA[(k4 + 3) * SA_STRIDE + r] = a.w;
        }
        __syncthreads();

        float acc[8][8];
#pragma unroll
        for (int i = 0; i < 8; i++)
#pragma unroll
            for (int j = 0; j < 8; j++) acc[i][j] = 0.f;

#pragma unroll 4
        for (int k = 0; k < KS; k++) {
            float ar[8], br[8];
            *reinterpret_cast<float4*>(ar)     = *reinterpret_cast<const float4*>(&sA[k * SA_STRIDE + ty * 8]);
            *reinterpret_cast<float4*>(ar + 4) = *reinterpret_cast<const float4*>(&sA[k * SA_STRIDE + ty * 8 + 4]);
            *reinterpret_cast<float4*>(br)     = *reinterpret_cast<const float4*>(&sB[k * SB_STRIDE + tx * 8]);
            *reinterpret_cast<float4*>(br + 4) = *reinterpret_cast<const float4*>(&sB[k * SB_STRIDE + tx * 8 + 4]);
#pragma unroll
            for (int i = 0; i < 8; i++)
#pragma unroll
                for (int j = 0; j < 8; j++)
                    acc[i][j] += ar[i] * br[j];
        }

        const int row0 = ty * 8;
        const int col0 = bn + tx * 8;
#pragma unroll
        for (int i = 0; i < 8; i++) {
            float4 v0, v1;
            v0.x = acc[i][0]; v0.y = acc[i][1]; v0.z = acc[i][2]; v0.w = acc[i][3];
            v1.x = acc[i][4]; v1.y = acc[i][5]; v1.z = acc[i][6]; v1.w = acc[i][7];
            __stcg(reinterpret_cast<float4*>(&Cp[(size_t)(row0 + i) * G3 + col0]), v0);
            __stcg(reinterpret_cast<float4*>(&Cp[(size_t)(row0 + i) * G3 + col0 + 4]), v1);
        }
        grid_barrier();

        // ======== phase B: gate spread across ALL blocks ========
        if (has_gate) {
            const int b = gb;
            const int j4 = gj4;

            float4 ghr = make_float4(0.f, 0.f, 0.f, 0.f);
            float4 ghz = ghr, ghn = ghr;
#pragma unroll
            for (int s = 0; s < SPLITS; s++) {
                const float* base = g_cp + (size_t)s * (B_ * G3) + (size_t)b * G3 + j4;
                const float4 a = __ldcg(reinterpret_cast<const float4*>(base));
                const float4 c = __ldcg(reinterpret_cast<const float4*>(base + H_));
                const float4 d = __ldcg(reinterpret_cast<const float4*>(base + 2 * H_));
                ghr.x += a.x; ghr.y += a.y; ghr.z += a.z; ghr.w += a.w;
                ghz.x += c.x; ghz.y += c.y; ghz.z += c.z; ghz.w += c.w;
                ghn.x += d.x; ghn.y += d.y; ghn.z += d.z; ghn.w += d.w;
            }
            const float4 br = *reinterpret_cast<const float4*>(&b_hh[j4]);
            const float4 bz = *reinterpret_cast<const float4*>(&b_hh[H_ + j4]);
            const float4 bn2 = *reinterpret_cast<const float4*>(&b_hh[2 * H_ + j4]);

            const float* gxb = gx + ((size_t)b * T_ + t) * G3 + j4;
            const float4 xr = __ldcg(reinterpret_cast<const float4*>(gxb));
            const float4 xz = __ldcg(reinterpret_cast<const float4*>(gxb + H_));
            const float4 xn = __ldcg(reinterpret_cast<const float4*>(gxb + 2 * H_));

            const float4 hp = __ldcg(reinterpret_cast<const float4*>(&g_h[b * H_ + j4]));
            const bool m = t < lens[b];

            float4 hn;
            {
                float r = fast_sigmoid(xr.x + ghr.x + br.x);
                float z = fast_sigmoid(xz.x + ghz.x + bz.x);
                float n = fast_tanh(xn.x + r * (ghn.x + bn2.x));
                hn.x = (1.f - z) * n + z * hp.x;
            }
            {
                float r = fast_sigmoid(xr.y + ghr.y + br.y);
                float z = fast_sigmoid(xz.y + ghz.y + bz.y);
                float n = fast_tanh(xn.y + r * (ghn.y + bn2.y));
                hn.y = (1.f - z) * n + z * hp.y;
            }
            {
                float r = fast_sigmoid(xr.z + ghr.z + br.z);
                float z = fast_sigmoid(xz.z + ghz.z + bz.z);
                float n = fast_tanh(xn.z + r * (ghn.z + bn2.z));
                hn.z = (1.f - z) * n + z * hp.z;
            }
            {
                float r = fast_sigmoid(xr.w + ghr.w + br.w);
                float z = fast_sigmoid(xz.w + ghz.w + bz.w);
                float n = fast_tanh(xn.w + r * (ghn.w + bn2.w));
                hn.w = (1.f - z) * n + z * hp.w;
            }

            const float4 hout = m ? hn : hp;
            const float4 yout = m ? hn : make_float4(0.f, 0.f, 0.f, 0.f);
            __stcg(reinterpret_cast<float4*>(&g_h[b * H_ + j4]), hout);
            __stcg(reinterpret_cast<float4*>(&out[((size_t)b * T_ + t) * H_ + j4]), yout);
        }
        grid_barrier();
    }

    // hidden = output[:, T-1, :]
    for (int idx = gtid; idx < B_ * H_; idx += NBLK * NTHR) {
        const int b = idx >> 10;
        const int j = idx & 1023;
        out[(size_t)B_ * T_ * H_ + idx] =
            __ldcg(&out[((size_t)b * T_ + (T_ - 1)) * H_ + j]);
    }
}

// ---------------- launch ------------------------------------------------------
extern "C" void kernel_launch(void* const* d_in, const int* in_sizes, int n_in,
                              void* d_out, int out_size)
{
    const float* input = (const float*)d_in[0];
    const int*   lens  = (const int*)  d_in[1];
    const float* W_p   = (const float*)d_in[2];
    const float* b_p   = (const float*)d_in[3];
    const float* w_ih  = (const float*)d_in[4];
    const float* w_hh  = (const float*)d_in[5];
    const float* b_ih  = (const float*)d_in[6];
    const float* b_hh  = (const float*)d_in[7];
    float* out = (float*)d_out;

    float *emb, *gx;
    cudaGetSymbolAddress((void**)&emb, g_emb);
    cudaGetSymbolAddress((void**)&gx,  g_gx);

    // emb = input @ W_p^T + b_p          [16384 x 1024], K=2048
    dim3 g1(H_ / 128, (B_ * T_) / 128);
    sgemm_nt_bias<<<g1, 256>>>(input, W_p, b_p, emb, B_ * T_, H_, F_IN_);

    // gx = emb @ w_ih^T + b_ih           [16384 x 3072], K=1024
    dim3 g2(G3 / 128, (B_ * T_) / 128);
    sgemm_nt_bias<<<g2, 256>>>(emb, w_ih, b_ih, gx, B_ * T_, G3, H_);

    // persistent fused scan (h0 init + 256 steps + hidden copy)
    static int smem_set = 0;
    if (!smem_set) {
        cudaFuncSetAttribute(gru_scan_persistent,
                             cudaFuncAttributeMaxDynamicSharedMemorySize, SMEM_BYTES);
        smem_set = 1;
    }
    gru_scan_persistent<<<NBLK, NTHR, SMEM_BYTES>>>(gx, w_hh, b_hh, lens, out);
}